// round 3
// baseline (speedup 1.0000x reference)
#include <cuda_runtime.h>
#include <cstdint>

#define MAXN 100000
#define MAXE 1600000

// ---------------- device scratch (static: no allocations allowed) ----------------
__device__ int   g_deg[MAXN];
__device__ int   g_offs[MAXN];
__device__ int   g_cursor[MAXN];
__device__ int   g_partial[256];
__device__ int   g_csr[MAXE];
__device__ float g_aggx[(size_t)MAXN * 128];  // mean-aggregated x
__device__ float g_h[(size_t)MAXN * 128];     // layer-1 output (post ReLU)
__device__ float g_t2[(size_t)MAXN * 128];    // [h@W2l | h@W2r] per row

// ---------------- CSR construction ----------------
__global__ void k_zero_deg(int N) {
    int i = blockIdx.x * blockDim.x + threadIdx.x;
    if (i < N) g_deg[i] = 0;
}

__global__ void k_count(const int* __restrict__ ei, int E) {
    int e = blockIdx.x * blockDim.x + threadIdx.x;
    if (e < E) atomicAdd(&g_deg[ei[E + e]], 1);
}

// partial sums over chunks of 1024
__global__ void k_scan_partial(int N) {
    __shared__ int red[256];
    int base = blockIdx.x * 1024;
    int s = 0;
    for (int i = threadIdx.x; i < 1024; i += 256) {
        int idx = base + i;
        s += (idx < N) ? g_deg[idx] : 0;
    }
    red[threadIdx.x] = s;
    __syncthreads();
    for (int off = 128; off > 0; off >>= 1) {
        if (threadIdx.x < off) red[threadIdx.x] += red[threadIdx.x + off];
        __syncthreads();
    }
    if (threadIdx.x == 0) g_partial[blockIdx.x] = red[0];
}

__global__ void k_scan_mid(int NB) {
    if (threadIdx.x == 0 && blockIdx.x == 0) {
        int run = 0;
        for (int b = 0; b < NB; b++) {
            int t = g_partial[b];
            g_partial[b] = run;
            run += t;
        }
    }
}

__global__ void k_scan_final(int N) {
    __shared__ int ws[32];
    int i = blockIdx.x * 1024 + threadIdx.x;
    int v = (i < N) ? g_deg[i] : 0;
    int lane = threadIdx.x & 31, w = threadIdx.x >> 5;
    int inc = v;
#pragma unroll
    for (int off = 1; off < 32; off <<= 1) {
        int n = __shfl_up_sync(0xffffffffu, inc, off);
        if (lane >= off) inc += n;
    }
    if (lane == 31) ws[w] = inc;
    __syncthreads();
    if (w == 0) {
        int x = ws[lane];
#pragma unroll
        for (int off = 1; off < 32; off <<= 1) {
            int n = __shfl_up_sync(0xffffffffu, x, off);
            if (lane >= off) x += n;
        }
        ws[lane] = x;
    }
    __syncthreads();
    int excl = inc - v + (w > 0 ? ws[w - 1] : 0) + g_partial[blockIdx.x];
    if (i < N) {
        g_offs[i] = excl;
        g_cursor[i] = excl;
    }
}

__global__ void k_fill_csr(const int* __restrict__ ei, int E) {
    int e = blockIdx.x * blockDim.x + threadIdx.x;
    if (e < E) {
        int s = ei[e];
        int d = ei[E + e];
        int pos = atomicAdd(&g_cursor[d], 1);
        g_csr[pos] = s;
    }
}

// ---------------- aggregation kernels ----------------
// mean over neighbors of x (128-dim). 1 warp per node, 1 float4 per lane.
__global__ void k_agg1(const float* __restrict__ x, int N) {
    int node = blockIdx.x * 8 + (threadIdx.x >> 5);
    if (node >= N) return;
    int lane = threadIdx.x & 31;
    int off = g_offs[node];
    int d = g_deg[node];
    float4 acc = make_float4(0.f, 0.f, 0.f, 0.f);
    int e = 0;
    for (; e + 1 < d; e += 2) {
        int j0 = g_csr[off + e];
        int j1 = g_csr[off + e + 1];
        float4 v0 = *reinterpret_cast<const float4*>(x + (size_t)j0 * 128 + lane * 4);
        float4 v1 = *reinterpret_cast<const float4*>(x + (size_t)j1 * 128 + lane * 4);
        acc.x += v0.x + v1.x; acc.y += v0.y + v1.y;
        acc.z += v0.z + v1.z; acc.w += v0.w + v1.w;
    }
    if (e < d) {
        int j0 = g_csr[off + e];
        float4 v0 = *reinterpret_cast<const float4*>(x + (size_t)j0 * 128 + lane * 4);
        acc.x += v0.x; acc.y += v0.y; acc.z += v0.z; acc.w += v0.w;
    }
    float inv = 1.0f / fmaxf((float)d, 1.0f);
    float4 r = make_float4(acc.x * inv, acc.y * inv, acc.z * inv, acc.w * inv);
    *reinterpret_cast<float4*>(g_aggx + (size_t)node * 128 + lane * 4) = r;
}

// out[i, c] = mean_j t2[j, c] + b2[c] + t2[i, 64+c], c in [0,64). 1 warp/node, float2/lane.
__global__ void k_agg2(const float* __restrict__ b2, float* __restrict__ out, int N) {
    int node = blockIdx.x * 8 + (threadIdx.x >> 5);
    if (node >= N) return;
    int lane = threadIdx.x & 31;
    int off = g_offs[node];
    int d = g_deg[node];
    float2 acc = make_float2(0.f, 0.f);
    int e = 0;
    for (; e + 1 < d; e += 2) {
        int j0 = g_csr[off + e];
        int j1 = g_csr[off + e + 1];
        float2 v0 = *reinterpret_cast<const float2*>(g_t2 + (size_t)j0 * 128 + lane * 2);
        float2 v1 = *reinterpret_cast<const float2*>(g_t2 + (size_t)j1 * 128 + lane * 2);
        acc.x += v0.x + v1.x; acc.y += v0.y + v1.y;
    }
    if (e < d) {
        int j0 = g_csr[off + e];
        float2 v0 = *reinterpret_cast<const float2*>(g_t2 + (size_t)j0 * 128 + lane * 2);
        acc.x += v0.x; acc.y += v0.y;
    }
    float inv = 1.0f / fmaxf((float)d, 1.0f);
    float2 bb = *reinterpret_cast<const float2*>(b2 + lane * 2);
    float2 rr = *reinterpret_cast<const float2*>(g_t2 + (size_t)node * 128 + 64 + lane * 2);
    float2 o = make_float2(acc.x * inv + bb.x + rr.x, acc.y * inv + bb.y + rr.y);
    *reinterpret_cast<float2*>(out + (size_t)node * 64 + lane * 2) = o;
}

// ---------------- tf32 tensor-core GEMM (3xTF32 for fp32 accuracy) ----------------
#define BM 64
#define GT 128
#define ALD 132   // As stride: conflict-free A-fragment loads ((4*gid+tig)%32 distinct)
#define WLD 132
#define SMEM_FLOATS (BM * ALD + 128 * WLD)

__device__ __forceinline__ void mma_tf32(float c[4], const uint32_t a[4], const uint32_t b[2]) {
    asm volatile(
        "mma.sync.aligned.m16n8k8.row.col.f32.tf32.tf32.f32 "
        "{%0,%1,%2,%3},{%4,%5,%6,%7},{%8,%9},{%0,%1,%2,%3};\n"
        : "+f"(c[0]), "+f"(c[1]), "+f"(c[2]), "+f"(c[3])
        : "r"(a[0]), "r"(a[1]), "r"(a[2]), "r"(a[3]), "r"(b[0]), "r"(b[1]));
}

__device__ __forceinline__ uint32_t tf_hi(float x) {
    return __float_as_uint(x) & 0xffffe000u;
}

__device__ __forceinline__ void load_A_tile(float* As, const float* __restrict__ A, int m0, int M) {
    for (int idx = threadIdx.x; idx < BM * 32; idx += GT) {
        int r = idx >> 5, q = (idx & 31) << 2;
        float4 v = make_float4(0.f, 0.f, 0.f, 0.f);
        int row = m0 + r;
        if (row < M) v = *reinterpret_cast<const float4*>(A + (size_t)row * 128 + q);
        *reinterpret_cast<float4*>(As + r * ALD + q) = v;
    }
}

__device__ __forceinline__ void load_W_full(float* Ws, const float* __restrict__ W) {
    for (int idx = threadIdx.x; idx < 128 * 32; idx += GT) {
        int r = idx >> 5, q = (idx & 31) << 2;
        float4 v = *reinterpret_cast<const float4*>(W + r * 128 + q);
        *reinterpret_cast<float4*>(Ws + r * WLD + q) = v;
    }
}

// Ws[k][n] = n<64 ? Wa[k][n] : Wb[k][n-64]  (Wa, Wb are [128,64] row-major)
__device__ __forceinline__ void load_W_split(float* Ws, const float* __restrict__ Wa,
                                             const float* __restrict__ Wb) {
    for (int idx = threadIdx.x; idx < 128 * 32; idx += GT) {
        int r = idx >> 5, q = idx & 31;
        float4 v;
        if (q < 16) v = *reinterpret_cast<const float4*>(Wa + r * 64 + q * 4);
        else        v = *reinterpret_cast<const float4*>(Wb + r * 64 + (q - 16) * 4);
        *reinterpret_cast<float4*>(Ws + r * WLD + q * 4) = v;
    }
}

// one full K=128 pass accumulating into c (3xTF32)
__device__ __forceinline__ void kloop(const float* __restrict__ As, const float* __restrict__ Ws,
                                      float c[16][4], int wr, int gid, int tig) {
#pragma unroll 2
    for (int ks = 0; ks < 16; ks++) {
        int k0 = ks * 8;
        float af[4];
        af[0] = As[(wr + gid) * ALD + k0 + tig];
        af[1] = As[(wr + gid + 8) * ALD + k0 + tig];
        af[2] = As[(wr + gid) * ALD + k0 + tig + 4];
        af[3] = As[(wr + gid + 8) * ALD + k0 + tig + 4];
        uint32_t ah[4], al[4];
#pragma unroll
        for (int i = 0; i < 4; i++) {
            ah[i] = tf_hi(af[i]);
            al[i] = __float_as_uint(af[i] - __uint_as_float(ah[i]));
        }
#pragma unroll
        for (int nt = 0; nt < 16; nt++) {
            float b0 = Ws[(k0 + tig) * WLD + nt * 8 + gid];
            float b1 = Ws[(k0 + tig + 4) * WLD + nt * 8 + gid];
            uint32_t bh[2], bl[2];
            bh[0] = tf_hi(b0); bl[0] = __float_as_uint(b0 - __uint_as_float(bh[0]));
            bh[1] = tf_hi(b1); bl[1] = __float_as_uint(b1 - __uint_as_float(bh[1]));
            mma_tf32(c[nt], ah, bh);
            mma_tf32(c[nt], ah, bl);
            mma_tf32(c[nt], al, bh);
        }
    }
}

// h = relu(aggx @ W1l + x @ W1r + b1)
__global__ void k_gemm1(const float* __restrict__ x, const float* __restrict__ W1l,
                        const float* __restrict__ W1r, const float* __restrict__ b1, int M) {
    extern __shared__ float sm[];
    float* As = sm;
    float* Ws = sm + BM * ALD;
    int m0 = blockIdx.x * BM;
    int lane = threadIdx.x & 31;
    int wid = threadIdx.x >> 5;
    int gid = lane >> 2, tig = lane & 3, wr = wid * 16;

    float c[16][4];
#pragma unroll
    for (int i = 0; i < 16; i++)
#pragma unroll
        for (int j = 0; j < 4; j++) c[i][j] = 0.f;

    // phase 0: aggx @ W1l
    load_A_tile(As, g_aggx, m0, M);
    load_W_full(Ws, W1l);
    __syncthreads();
    kloop(As, Ws, c, wr, gid, tig);
    __syncthreads();
    // phase 1: x @ W1r
    load_A_tile(As, x, m0, M);
    load_W_full(Ws, W1r);
    __syncthreads();
    kloop(As, Ws, c, wr, gid, tig);

    int r0 = m0 + wr + gid, r1 = r0 + 8;
#pragma unroll
    for (int nt = 0; nt < 16; nt++) {
        int col = nt * 8 + tig * 2;
        float2 bb = *reinterpret_cast<const float2*>(b1 + col);
        if (r0 < M) {
            float2 v = make_float2(fmaxf(c[nt][0] + bb.x, 0.f), fmaxf(c[nt][1] + bb.y, 0.f));
            *reinterpret_cast<float2*>(g_h + (size_t)r0 * 128 + col) = v;
        }
        if (r1 < M) {
            float2 v = make_float2(fmaxf(c[nt][2] + bb.x, 0.f), fmaxf(c[nt][3] + bb.y, 0.f));
            *reinterpret_cast<float2*>(g_h + (size_t)r1 * 128 + col) = v;
        }
    }
}

// t2 = [h @ W2l | h @ W2r]   (no bias here)
__global__ void k_gemm2(const float* __restrict__ W2l, const float* __restrict__ W2r, int M) {
    extern __shared__ float sm[];
    float* As = sm;
    float* Ws = sm + BM * ALD;
    int m0 = blockIdx.x * BM;
    int lane = threadIdx.x & 31;
    int wid = threadIdx.x >> 5;
    int gid = lane >> 2, tig = lane & 3, wr = wid * 16;

    float c[16][4];
#pragma unroll
    for (int i = 0; i < 16; i++)
#pragma unroll
        for (int j = 0; j < 4; j++) c[i][j] = 0.f;

    load_A_tile(As, g_h, m0, M);
    load_W_split(Ws, W2l, W2r);
    __syncthreads();
    kloop(As, Ws, c, wr, gid, tig);

    int r0 = m0 + wr + gid, r1 = r0 + 8;
#pragma unroll
    for (int nt = 0; nt < 16; nt++) {
        int col = nt * 8 + tig * 2;
        if (r0 < M) {
            float2 v = make_float2(c[nt][0], c[nt][1]);
            *reinterpret_cast<float2*>(g_t2 + (size_t)r0 * 128 + col) = v;
        }
        if (r1 < M) {
            float2 v = make_float2(c[nt][2], c[nt][3]);
            *reinterpret_cast<float2*>(g_t2 + (size_t)r1 * 128 + col) = v;
        }
    }
}

// ---------------- launcher ----------------
extern "C" void kernel_launch(void* const* d_in, const int* in_sizes, int n_in,
                              void* d_out, int out_size) {
    const float* x   = (const float*)d_in[0];
    const float* W1l = (const float*)d_in[1];
    const float* b1  = (const float*)d_in[2];
    const float* W1r = (const float*)d_in[3];
    const float* W2l = (const float*)d_in[4];
    const float* b2  = (const float*)d_in[5];
    const float* W2r = (const float*)d_in[6];
    const int*   ei  = (const int*)d_in[7];
    float* out = (float*)d_out;

    int N = in_sizes[0] / 128;
    int E = in_sizes[7] / 2;

    // CSR build (reused by both layers)
    k_zero_deg<<<(N + 255) / 256, 256>>>(N);
    k_count<<<(E + 255) / 256, 256>>>(ei, E);
    int NB = (N + 1023) / 1024;
    k_scan_partial<<<NB, 256>>>(N);
    k_scan_mid<<<1, 32>>>(NB);
    k_scan_final<<<NB, 1024>>>(N);
    k_fill_csr<<<(E + 255) / 256, 256>>>(ei, E);

    // layer 1: aggregate x, then fused dual-GEMM + bias + ReLU
    k_agg1<<<(N + 7) / 8, 256>>>(x, N);

    size_t smem = SMEM_FLOATS * sizeof(float);
    cudaFuncSetAttribute(k_gemm1, cudaFuncAttributeMaxDynamicSharedMemorySize, (int)smem);
    cudaFuncSetAttribute(k_gemm2, cudaFuncAttributeMaxDynamicSharedMemorySize, (int)smem);
    int GB = (N + BM - 1) / BM;
    k_gemm1<<<GB, GT, smem>>>(x, W1l, W1r, b1, N);

    // layer 2: GEMM first (64-dim messages halve gather traffic), then aggregate + epilogue
    k_gemm2<<<GB, GT, smem>>>(W2l, W2r, N);
    k_agg2<<<(N + 7) / 8, 256>>>(b2, out, N);
}

// round 4
// speedup vs baseline: 1.0223x; 1.0223x over previous
#include <cuda_runtime.h>
#include <cstdint>

#define MAXN 100000
#define MAXE 1600000

// ---------------- device scratch (static: no allocations allowed) ----------------
__device__ int   g_deg[MAXN];
__device__ int   g_offs[MAXN];
__device__ int   g_cursor[MAXN];
__device__ int   g_total;
__device__ int   g_csr[MAXE];
__device__ float g_aggx[(size_t)MAXN * 128];  // mean-aggregated x
__device__ float g_h[(size_t)MAXN * 128];     // layer-1 output (post ReLU)
__device__ float g_t2[(size_t)MAXN * 128];    // [h@W2l | h@W2r] per row

// ---------------- CSR construction ----------------
__global__ void k_zero_deg(int N) {
    int i = blockIdx.x * blockDim.x + threadIdx.x;
    if (i < N) g_deg[i] = 0;
    if (i == 0) g_total = 0;
}

__global__ void k_count(const int* __restrict__ ei, int E) {
    int e = blockIdx.x * blockDim.x + threadIdx.x;
    if (e < E) atomicAdd(&g_deg[ei[E + e]], 1);
}

// Order-free offset allocation: block-local scan, block base via one atomicAdd.
// (Offsets need only be disjoint contiguous ranges; global order is irrelevant.)
__global__ void k_alloc_offs(int N) {
    __shared__ int ws[32];
    __shared__ int base;
    int i = blockIdx.x * 1024 + threadIdx.x;
    int v = (i < N) ? g_deg[i] : 0;
    int lane = threadIdx.x & 31, w = threadIdx.x >> 5;
    int inc = v;
#pragma unroll
    for (int off = 1; off < 32; off <<= 1) {
        int n = __shfl_up_sync(0xffffffffu, inc, off);
        if (lane >= off) inc += n;
    }
    if (lane == 31) ws[w] = inc;
    __syncthreads();
    if (w == 0) {
        int s = ws[lane];
#pragma unroll
        for (int off = 1; off < 32; off <<= 1) {
            int n = __shfl_up_sync(0xffffffffu, s, off);
            if (lane >= off) s += n;
        }
        ws[lane] = s;
    }
    __syncthreads();
    if (threadIdx.x == 0) base = atomicAdd(&g_total, ws[31]);
    int warpBase = (w > 0) ? ws[w - 1] : 0;
    __syncthreads();
    int excl = base + warpBase + inc - v;
    if (i < N) {
        g_offs[i] = excl;
        g_cursor[i] = excl;
    }
}

__global__ void k_fill_csr(const int* __restrict__ ei, int E) {
    int e = blockIdx.x * blockDim.x + threadIdx.x;
    if (e < E) {
        int s = ei[e];
        int d = ei[E + e];
        int pos = atomicAdd(&g_cursor[d], 1);
        g_csr[pos] = s;
    }
}

// ---------------- aggregation kernels ----------------
// mean over neighbors of x (128-dim). 1 warp per node, 1 float4 per lane, MLP=4.
__global__ void k_agg1(const float* __restrict__ x, int N) {
    int node = blockIdx.x * 8 + (threadIdx.x >> 5);
    if (node >= N) return;
    int lane = threadIdx.x & 31;
    int off = g_offs[node];
    int d = g_deg[node];
    float4 acc = make_float4(0.f, 0.f, 0.f, 0.f);
    int e = 0;
    for (; e + 3 < d; e += 4) {
        int j0 = g_csr[off + e];
        int j1 = g_csr[off + e + 1];
        int j2 = g_csr[off + e + 2];
        int j3 = g_csr[off + e + 3];
        float4 v0 = *reinterpret_cast<const float4*>(x + (size_t)j0 * 128 + lane * 4);
        float4 v1 = *reinterpret_cast<const float4*>(x + (size_t)j1 * 128 + lane * 4);
        float4 v2 = *reinterpret_cast<const float4*>(x + (size_t)j2 * 128 + lane * 4);
        float4 v3 = *reinterpret_cast<const float4*>(x + (size_t)j3 * 128 + lane * 4);
        acc.x += (v0.x + v1.x) + (v2.x + v3.x);
        acc.y += (v0.y + v1.y) + (v2.y + v3.y);
        acc.z += (v0.z + v1.z) + (v2.z + v3.z);
        acc.w += (v0.w + v1.w) + (v2.w + v3.w);
    }
    for (; e < d; e++) {
        int j0 = g_csr[off + e];
        float4 v0 = *reinterpret_cast<const float4*>(x + (size_t)j0 * 128 + lane * 4);
        acc.x += v0.x; acc.y += v0.y; acc.z += v0.z; acc.w += v0.w;
    }
    float inv = 1.0f / fmaxf((float)d, 1.0f);
    float4 r = make_float4(acc.x * inv, acc.y * inv, acc.z * inv, acc.w * inv);
    *reinterpret_cast<float4*>(g_aggx + (size_t)node * 128 + lane * 4) = r;
}

// out[i, c] = mean_j t2[j, c] + b2[c] + t2[i, 64+c], c in [0,64). 1 warp/node, MLP=4.
__global__ void k_agg2(const float* __restrict__ b2, float* __restrict__ out, int N) {
    int node = blockIdx.x * 8 + (threadIdx.x >> 5);
    if (node >= N) return;
    int lane = threadIdx.x & 31;
    int off = g_offs[node];
    int d = g_deg[node];
    float2 acc = make_float2(0.f, 0.f);
    int e = 0;
    for (; e + 3 < d; e += 4) {
        int j0 = g_csr[off + e];
        int j1 = g_csr[off + e + 1];
        int j2 = g_csr[off + e + 2];
        int j3 = g_csr[off + e + 3];
        float2 v0 = *reinterpret_cast<const float2*>(g_t2 + (size_t)j0 * 128 + lane * 2);
        float2 v1 = *reinterpret_cast<const float2*>(g_t2 + (size_t)j1 * 128 + lane * 2);
        float2 v2 = *reinterpret_cast<const float2*>(g_t2 + (size_t)j2 * 128 + lane * 2);
        float2 v3 = *reinterpret_cast<const float2*>(g_t2 + (size_t)j3 * 128 + lane * 2);
        acc.x += (v0.x + v1.x) + (v2.x + v3.x);
        acc.y += (v0.y + v1.y) + (v2.y + v3.y);
    }
    for (; e < d; e++) {
        int j0 = g_csr[off + e];
        float2 v0 = *reinterpret_cast<const float2*>(g_t2 + (size_t)j0 * 128 + lane * 2);
        acc.x += v0.x; acc.y += v0.y;
    }
    float inv = 1.0f / fmaxf((float)d, 1.0f);
    float2 bb = *reinterpret_cast<const float2*>(b2 + lane * 2);
    float2 rr = *reinterpret_cast<const float2*>(g_t2 + (size_t)node * 128 + 64 + lane * 2);
    float2 o = make_float2(acc.x * inv + bb.x + rr.x, acc.y * inv + bb.y + rr.y);
    *reinterpret_cast<float2*>(out + (size_t)node * 64 + lane * 2) = o;
}

// ---------------- tf32 tensor-core GEMM (3xTF32 for fp32 accuracy) ----------------
// BM=128, 4 warps, 32 rows per warp (two stacked m16 tiles): halves smem B traffic
// per output row. LD=136 (mod 32 == 8) -> A-frag banks 8*gid+tig, B-frag banks
// 8*tig+gid: both fully conflict-free (previous 132 padding was 2-way conflicted).
#define BM 128
#define GT 128
#define LD 136
#define SMEM_FLOATS (2 * 128 * LD)

__device__ __forceinline__ void mma_tf32(float* c, const uint32_t a[4], const uint32_t b[2]) {
    asm volatile(
        "mma.sync.aligned.m16n8k8.row.col.f32.tf32.tf32.f32 "
        "{%0,%1,%2,%3},{%4,%5,%6,%7},{%8,%9},{%0,%1,%2,%3};\n"
        : "+f"(c[0]), "+f"(c[1]), "+f"(c[2]), "+f"(c[3])
        : "r"(a[0]), "r"(a[1]), "r"(a[2]), "r"(a[3]), "r"(b[0]), "r"(b[1]));
}

__device__ __forceinline__ uint32_t tf_hi(float x) {
    return __float_as_uint(x) & 0xffffe000u;
}

__device__ __forceinline__ void load_A_tile(float* As, const float* __restrict__ A, int m0, int M) {
    for (int idx = threadIdx.x; idx < BM * 32; idx += GT) {
        int r = idx >> 5, q = (idx & 31) << 2;
        float4 v = make_float4(0.f, 0.f, 0.f, 0.f);
        int row = m0 + r;
        if (row < M) v = *reinterpret_cast<const float4*>(A + (size_t)row * 128 + q);
        *reinterpret_cast<float4*>(As + r * LD + q) = v;
    }
}

__device__ __forceinline__ void load_W_full(float* Ws, const float* __restrict__ W) {
    for (int idx = threadIdx.x; idx < 128 * 32; idx += GT) {
        int r = idx >> 5, q = (idx & 31) << 2;
        float4 v = *reinterpret_cast<const float4*>(W + r * 128 + q);
        *reinterpret_cast<float4*>(Ws + r * LD + q) = v;
    }
}

// Ws[k][n] = n<64 ? Wa[k][n] : Wb[k][n-64]  (Wa, Wb are [128,64] row-major)
__device__ __forceinline__ void load_W_split(float* Ws, const float* __restrict__ Wa,
                                             const float* __restrict__ Wb) {
    for (int idx = threadIdx.x; idx < 128 * 32; idx += GT) {
        int r = idx >> 5, q = idx & 31;
        float4 v;
        if (q < 16) v = *reinterpret_cast<const float4*>(Wa + r * 64 + q * 4);
        else        v = *reinterpret_cast<const float4*>(Wb + r * 64 + (q - 16) * 4);
        *reinterpret_cast<float4*>(Ws + r * LD + q * 4) = v;
    }
}

// one full K=128 pass, 32 rows/warp, accumulating into c[16][8] (3xTF32)
__device__ __forceinline__ void kloop32(const float* __restrict__ As, const float* __restrict__ Ws,
                                        float c[16][8], int wr, int gid, int tig) {
#pragma unroll 2
    for (int ks = 0; ks < 16; ks++) {
        int k0 = ks * 8;
        const float* Ab = As + k0 + tig;
        float af[8];
        af[0] = Ab[(wr + gid) * LD];
        af[1] = Ab[(wr + gid + 8) * LD];
        af[2] = Ab[(wr + gid) * LD + 4];
        af[3] = Ab[(wr + gid + 8) * LD + 4];
        af[4] = Ab[(wr + gid + 16) * LD];
        af[5] = Ab[(wr + gid + 24) * LD];
        af[6] = Ab[(wr + gid + 16) * LD + 4];
        af[7] = Ab[(wr + gid + 24) * LD + 4];
        uint32_t ah[8], al[8];
#pragma unroll
        for (int i = 0; i < 8; i++) {
            ah[i] = tf_hi(af[i]);
            al[i] = __float_as_uint(af[i] - __uint_as_float(ah[i]));
        }
#pragma unroll
        for (int nt = 0; nt < 16; nt++) {
            float b0 = Ws[(k0 + tig) * LD + nt * 8 + gid];
            float b1 = Ws[(k0 + tig + 4) * LD + nt * 8 + gid];
            uint32_t bh[2], bl[2];
            bh[0] = tf_hi(b0); bl[0] = __float_as_uint(b0 - __uint_as_float(bh[0]));
            bh[1] = tf_hi(b1); bl[1] = __float_as_uint(b1 - __uint_as_float(bh[1]));
            mma_tf32(c[nt] + 0, ah + 0, bh);
            mma_tf32(c[nt] + 0, ah + 0, bl);
            mma_tf32(c[nt] + 0, al + 0, bh);
            mma_tf32(c[nt] + 4, ah + 4, bh);
            mma_tf32(c[nt] + 4, ah + 4, bl);
            mma_tf32(c[nt] + 4, al + 4, bh);
        }
    }
}

// h = relu(aggx @ W1l + x @ W1r + b1)
__global__ void __launch_bounds__(GT, 1)
k_gemm1(const float* __restrict__ x, const float* __restrict__ W1l,
        const float* __restrict__ W1r, const float* __restrict__ b1, int M) {
    extern __shared__ float sm[];
    float* As = sm;
    float* Ws = sm + 128 * LD;
    int m0 = blockIdx.x * BM;
    int lane = threadIdx.x & 31;
    int wid = threadIdx.x >> 5;
    int gid = lane >> 2, tig = lane & 3, wr = wid * 32;

    float c[16][8];
#pragma unroll
    for (int i = 0; i < 16; i++)
#pragma unroll
        for (int j = 0; j < 8; j++) c[i][j] = 0.f;

    // phase 0: aggx @ W1l
    load_A_tile(As, g_aggx, m0, M);
    load_W_full(Ws, W1l);
    __syncthreads();
    kloop32(As, Ws, c, wr, gid, tig);
    __syncthreads();
    // phase 1: x @ W1r
    load_A_tile(As, x, m0, M);
    load_W_full(Ws, W1r);
    __syncthreads();
    kloop32(As, Ws, c, wr, gid, tig);

    int rb = m0 + wr + gid;
#pragma unroll
    for (int nt = 0; nt < 16; nt++) {
        int col = nt * 8 + tig * 2;
        float2 bb = *reinterpret_cast<const float2*>(b1 + col);
#pragma unroll
        for (int t = 0; t < 4; t++) {
            int r = rb + t * 8;
            if (r < M) {
                float2 v = make_float2(fmaxf(c[nt][t * 2] + bb.x, 0.f),
                                       fmaxf(c[nt][t * 2 + 1] + bb.y, 0.f));
                *reinterpret_cast<float2*>(g_h + (size_t)r * 128 + col) = v;
            }
        }
    }
}

// t2 = [h @ W2l | h @ W2r]   (no bias here)
__global__ void __launch_bounds__(GT, 1)
k_gemm2(const float* __restrict__ W2l, const float* __restrict__ W2r, int M) {
    extern __shared__ float sm[];
    float* As = sm;
    float* Ws = sm + 128 * LD;
    int m0 = blockIdx.x * BM;
    int lane = threadIdx.x & 31;
    int wid = threadIdx.x >> 5;
    int gid = lane >> 2, tig = lane & 3, wr = wid * 32;

    float c[16][8];
#pragma unroll
    for (int i = 0; i < 16; i++)
#pragma unroll
        for (int j = 0; j < 8; j++) c[i][j] = 0.f;

    load_A_tile(As, g_h, m0, M);
    load_W_split(Ws, W2l, W2r);
    __syncthreads();
    kloop32(As, Ws, c, wr, gid, tig);

    int rb = m0 + wr + gid;
#pragma unroll
    for (int nt = 0; nt < 16; nt++) {
        int col = nt * 8 + tig * 2;
#pragma unroll
        for (int t = 0; t < 4; t++) {
            int r = rb + t * 8;
            if (r < M) {
                float2 v = make_float2(c[nt][t * 2], c[nt][t * 2 + 1]);
                *reinterpret_cast<float2*>(g_t2 + (size_t)r * 128 + col) = v;
            }
        }
    }
}

// ---------------- launcher ----------------
extern "C" void kernel_launch(void* const* d_in, const int* in_sizes, int n_in,
                              void* d_out, int out_size) {
    const float* x   = (const float*)d_in[0];
    const float* W1l = (const float*)d_in[1];
    const float* b1  = (const float*)d_in[2];
    const float* W1r = (const float*)d_in[3];
    const float* W2l = (const float*)d_in[4];
    const float* b2  = (const float*)d_in[5];
    const float* W2r = (const float*)d_in[6];
    const int*   ei  = (const int*)d_in[7];
    float* out = (float*)d_out;

    int N = in_sizes[0] / 128;
    int E = in_sizes[7] / 2;

    // CSR build (reused by both layers)
    k_zero_deg<<<(N + 255) / 256, 256>>>(N);
    k_count<<<(E + 255) / 256, 256>>>(ei, E);
    k_alloc_offs<<<(N + 1023) / 1024, 1024>>>(N);
    k_fill_csr<<<(E + 255) / 256, 256>>>(ei, E);

    // layer 1: aggregate x, then fused dual-GEMM + bias + ReLU
    k_agg1<<<(N + 7) / 8, 256>>>(x, N);

    size_t smem = SMEM_FLOATS * sizeof(float);
    cudaFuncSetAttribute(k_gemm1, cudaFuncAttributeMaxDynamicSharedMemorySize, (int)smem);
    cudaFuncSetAttribute(k_gemm2, cudaFuncAttributeMaxDynamicSharedMemorySize, (int)smem);
    int GB = (N + BM - 1) / BM;
    k_gemm1<<<GB, GT, smem>>>(x, W1l, W1r, b1, N);

    // layer 2: GEMM first (64-dim messages halve gather traffic), then aggregate + epilogue
    k_gemm2<<<GB, GT, smem>>>(W2l, W2r, N);
    k_agg2<<<(N + 7) / 8, 256>>>(b2, out, N);
}